// round 2
// baseline (speedup 1.0000x reference)
#include <cuda_runtime.h>
#include <cuda_bf16.h>

// Problem constants
#define NN   10000
#define EE   320000
#define BB   64
#define IN_C 128
#define ECH  64
#define HID  256
#define MLPD 512
#define NCL  4
#define KMAX 576          // 2*HID + ECH
#define STATS_BLOCKS 40
#define ROWS_PER_STAT 250 // 40*250 = 10000

// ---------------- scratch (static device globals; no allocation) -------------
__device__ float g_X[NN * KMAX];       // concat(deg*h, agg_h, agg_ea) per layer
__device__ float g_pre[NN * HID];      // GEMM output / relu'd pre-BN
__device__ float g_h[NN * HID];        // layer output
__device__ float g_aggea[NN * ECH];    // sum of edge_attr into node (+ self loop 1s)
__device__ float g_deg[NN];            // indeg + 1 (self loop), as float
__device__ int   g_indeg[NN];
__device__ int   g_off[NN + 1];
__device__ int   g_pos[NN];
__device__ int   g_csrc[EE];           // src node per CSR slot
__device__ int   g_ceid[EE];           // edge id per CSR slot
__device__ float g_ps[STATS_BLOCKS * HID];
__device__ float g_pq[STATS_BLOCKS * HID];
__device__ float g_scale[HID];
__device__ float g_shift[HID];
__device__ int   g_bcnt[BB];
__device__ int   g_boff[BB];
__device__ float g_z[BB * (HID + 1 + IN_C)];   // 385 per graph
__device__ float g_fc1[BB * MLPD];

// ---------------- setup kernels ---------------------------------------------
__global__ void k_zero() {
    int i = blockIdx.x * blockDim.x + threadIdx.x;
    if (i < NN) g_indeg[i] = 0;
    if (i < BB) g_bcnt[i] = 0;
}

__global__ void k_hist(const int* __restrict__ dst, const int* __restrict__ batch) {
    int i = blockIdx.x * blockDim.x + threadIdx.x;
    if (i < EE) atomicAdd(&g_indeg[dst[i]], 1);
    if (i < NN) atomicAdd(&g_bcnt[batch[i]], 1);
}

// single-block exclusive scan over indeg (N=10000) + batch offsets
__global__ void k_scan() {
    __shared__ int sbuf[1024];
    int tid = threadIdx.x;
    int carry = 0;
    for (int base = 0; base < NN; base += 1024) {
        int i = base + tid;
        int v = (i < NN) ? g_indeg[i] : 0;
        int s = v;
        sbuf[tid] = s;
        __syncthreads();
        for (int ofs = 1; ofs < 1024; ofs <<= 1) {
            int add = (tid >= ofs) ? sbuf[tid - ofs] : 0;
            __syncthreads();
            s += add;
            sbuf[tid] = s;
            __syncthreads();
        }
        if (i < NN) {
            int excl = carry + s - v;
            g_off[i] = excl;
            g_pos[i] = excl;
            g_deg[i] = (float)(v + 1);
        }
        int total = sbuf[1023];
        __syncthreads();
        carry += total;
    }
    if (tid == 0) {
        g_off[NN] = carry;
        int c = 0;
        for (int b = 0; b < BB; b++) { g_boff[b] = c; c += g_bcnt[b]; }
    }
}

__global__ void k_fill(const int* __restrict__ src, const int* __restrict__ dst) {
    int e = blockIdx.x * blockDim.x + threadIdx.x;
    if (e >= EE) return;
    int d = dst[e];
    int p = atomicAdd(&g_pos[d], 1);
    g_csrc[p] = src[e];
    g_ceid[p] = e;
}

// per-node sum of incoming edge_attr + self-loop attr of 1.0
__global__ void k_aggea(const float* __restrict__ ea) {
    int v = blockIdx.x, t = threadIdx.x;  // blockDim = 64
    int s0 = g_off[v], s1 = g_off[v + 1];
    float acc = 1.0f;  // self-loop edge_attr filled with 1.0
    for (int j = s0; j < s1; j++) {
        acc += ea[(size_t)g_ceid[j] * ECH + t];
    }
    g_aggea[v * ECH + t] = acc;
}

// ---------------- per-layer kernels -----------------------------------------
// Build X[v,:] = [ deg[v]*h[v,:](D) | sum_in h[src,:](D) | agg_ea[v,:](64) ]
__global__ void k_agg(const float* __restrict__ hx, int D, int Kc) {
    const float* h = hx ? hx : g_h;
    int v = blockIdx.x, t = threadIdx.x;   // blockDim = D
    int s0 = g_off[v], s1 = g_off[v + 1];
    float hv = h[(size_t)v * D + t];
    float acc = hv;   // self loop contributes h[v]
    for (int j = s0; j < s1; j++) {
        int s = g_csrc[j];
        acc += h[(size_t)s * D + t];
    }
    float* Xr = g_X + (size_t)v * Kc;
    Xr[t]     = g_deg[v] * hv;
    Xr[D + t] = acc;
    if (t < ECH) Xr[2 * D + t] = g_aggea[v * ECH + t];
}

// SGEMM: g_pre[M,256] = g_X[M,K] @ W[K,256] + deg[m]*bias[n]
// BM=128, BN=64, BK=8, TM=8, TN=4, 256 threads
__global__ void __launch_bounds__(256) k_gemm(const float* __restrict__ W,
                                              const float* __restrict__ bias,
                                              int K) {
    const int M = NN;
    const int NCOLS = HID;
    __shared__ float As[8][128];
    __shared__ float Bs[8][64];

    int tid = threadIdx.x;
    int tx = tid & 15;          // 0..15 -> col groups of 4
    int ty = tid >> 4;          // 0..15 -> row groups of 8
    int row0 = blockIdx.x * 128;
    int col0 = blockIdx.y * 64;

    float acc[8][4];
#pragma unroll
    for (int i = 0; i < 8; i++)
#pragma unroll
        for (int j = 0; j < 4; j++) acc[i][j] = 0.f;

    int arow = tid >> 1;           // 0..127
    int acol = (tid & 1) * 4;      // 0 or 4
    int brow = tid >> 5;           // 0..7
    int bcol = (tid & 31) * 2;     // 0..62

    const float* Aptr = g_X + (size_t)(row0 + arow) * K + acol;
    const float* Bptr = W + (size_t)brow * NCOLS + col0 + bcol;
    bool arow_ok = (row0 + arow) < M;

    for (int k0 = 0; k0 < K; k0 += 8) {
        float4 av = arow_ok ? *(const float4*)Aptr : make_float4(0.f, 0.f, 0.f, 0.f);
        Aptr += 8;
        float2 bv = *(const float2*)Bptr;
        Bptr += 8 * NCOLS;
        As[acol + 0][arow] = av.x;
        As[acol + 1][arow] = av.y;
        As[acol + 2][arow] = av.z;
        As[acol + 3][arow] = av.w;
        *(float2*)&Bs[brow][bcol] = bv;
        __syncthreads();
#pragma unroll
        for (int k = 0; k < 8; k++) {
            float af[8], bf[4];
            *(float4*)&af[0] = *(const float4*)&As[k][ty * 8];
            *(float4*)&af[4] = *(const float4*)&As[k][ty * 8 + 4];
            *(float4*)&bf[0] = *(const float4*)&Bs[k][tx * 4];
#pragma unroll
            for (int i = 0; i < 8; i++)
#pragma unroll
                for (int j = 0; j < 4; j++) acc[i][j] = fmaf(af[i], bf[j], acc[i][j]);
        }
        __syncthreads();
    }

    int ncol = col0 + tx * 4;
    float4 bb = *(const float4*)&bias[ncol];
#pragma unroll
    for (int i = 0; i < 8; i++) {
        int m = row0 + ty * 8 + i;
        if (m >= M) continue;
        float d = g_deg[m];
        float4 o;
        o.x = acc[i][0] + d * bb.x;
        o.y = acc[i][1] + d * bb.y;
        o.z = acc[i][2] + d * bb.z;
        o.w = acc[i][3] + d * bb.w;
        *(float4*)&g_pre[(size_t)m * NCOLS + ncol] = o;
    }
}

// relu in place + per-channel partial sum / sumsq
__global__ void k_stats() {
    int t = threadIdx.x;           // 256
    int b = blockIdx.x;            // 40
    int r0 = b * ROWS_PER_STAT;
    int r1 = r0 + ROWS_PER_STAT;
    if (r1 > NN) r1 = NN;
    float s = 0.f, q = 0.f;
    for (int r = r0; r < r1; r++) {
        float v = g_pre[(size_t)r * HID + t];
        v = fmaxf(v, 0.f);
        g_pre[(size_t)r * HID + t] = v;
        s += v;
        q += v * v;
    }
    g_ps[b * HID + t] = s;
    g_pq[b * HID + t] = q;
}

__global__ void k_finalize(const float* __restrict__ gamma, const float* __restrict__ beta) {
    int t = threadIdx.x;  // 256
    float s = 0.f, q = 0.f;
    for (int b = 0; b < STATS_BLOCKS; b++) {
        s += g_ps[b * HID + t];
        q += g_pq[b * HID + t];
    }
    float inv_n = 1.0f / (float)NN;
    float mu = s * inv_n;
    float var = q * inv_n - mu * mu;
    float rs = rsqrtf(var + 1e-5f);
    float sc = rs * gamma[t];
    g_scale[t] = sc;
    g_shift[t] = beta[t] - mu * sc;
}

__global__ void k_norm() {
    int i = blockIdx.x * blockDim.x + threadIdx.x;
    if (i >= NN * HID) return;
    int c = i & (HID - 1);
    g_h[i] = fmaxf(g_pre[i] * g_scale[c] + g_shift[c], 0.f);
}

// ---------------- readout ---------------------------------------------------
__global__ void k_pool(const float* __restrict__ neighbor) {
    int b = blockIdx.x, t = threadIdx.x;   // 256
    int s0 = g_boff[b], c = g_bcnt[b];
    float acc = 0.f;
    for (int r = 0; r < c; r++) acc += g_h[(size_t)(s0 + r) * HID + t];
    float* zr = g_z + (size_t)b * (HID + 1 + IN_C);
    zr[t] = acc;
    if (t == 0) zr[HID] = (float)c / 40.0f;
    if (t < IN_C) zr[HID + 1 + t] = neighbor[b * IN_C + t];
}

__global__ void k_fc1(const float* __restrict__ w, const float* __restrict__ bias) {
    __shared__ float zs[HID + 1 + IN_C];   // 385
    int b = blockIdx.x, t = threadIdx.x;   // 512
    if (t < HID + 1 + IN_C) zs[t] = g_z[(size_t)b * (HID + 1 + IN_C) + t];
    __syncthreads();
    float acc = bias[t];
    for (int k = 0; k < HID + 1 + IN_C; k++) acc = fmaf(zs[k], w[(size_t)k * MLPD + t], acc);
    g_fc1[(size_t)b * MLPD + t] = fmaxf(acc, 0.f);
}

__global__ void k_fc2(const float* __restrict__ w, const float* __restrict__ bias,
                      float* __restrict__ out) {
    int b = blockIdx.x;
    int t = threadIdx.x;           // 128 = 4 warps
    int wrp = t >> 5;              // channel 0..3
    int lane = t & 31;
    float acc = 0.f;
    for (int k = lane; k < MLPD; k += 32)
        acc = fmaf(g_fc1[(size_t)b * MLPD + k], w[(size_t)k * NCL + wrp], acc);
#pragma unroll
    for (int o = 16; o > 0; o >>= 1) acc += __shfl_down_sync(0xFFFFFFFF, acc, o);
    if (lane == 0) out[b * NCL + wrp] = acc + bias[wrp];
}

// ---------------- launch -----------------------------------------------------
extern "C" void kernel_launch(void* const* d_in, const int* in_sizes, int n_in,
                              void* d_out, int out_size) {
    const float* x        = (const float*)d_in[0];
    const int*   ei       = (const int*)d_in[1];
    const float* ea       = (const float*)d_in[2];
    const int*   batch    = (const int*)d_in[3];
    const float* neighbor = (const float*)d_in[4];
    const float* W1  = (const float*)d_in[5];
    const float* b1  = (const float*)d_in[6];
    const float* g1  = (const float*)d_in[7];
    const float* be1 = (const float*)d_in[8];
    const float* W2  = (const float*)d_in[9];
    const float* b2  = (const float*)d_in[10];
    const float* g2  = (const float*)d_in[11];
    const float* be2 = (const float*)d_in[12];
    const float* W3  = (const float*)d_in[13];
    const float* b3  = (const float*)d_in[14];
    const float* g3  = (const float*)d_in[15];
    const float* be3 = (const float*)d_in[16];
    const float* fc1w = (const float*)d_in[17];
    const float* fc1b = (const float*)d_in[18];
    const float* fc2w = (const float*)d_in[19];
    const float* fc2b = (const float*)d_in[20];
    float* out = (float*)d_out;

    const int* src = ei;
    const int* dst = ei + EE;

    // CSR + degrees + batch offsets + edge-attr aggregation (layer-invariant)
    k_zero<<<(NN + 255) / 256, 256>>>();
    k_hist<<<(EE + 255) / 256, 256>>>(dst, batch);
    k_scan<<<1, 1024>>>();
    k_fill<<<(EE + 255) / 256, 256>>>(src, dst);
    k_aggea<<<NN, ECH>>>(ea);

    dim3 ggrid((NN + 127) / 128, HID / 64);
    int norm_grid = (NN * HID + 255) / 256;

    // layer 1 (D=128, K=320)
    k_agg<<<NN, IN_C>>>(x, IN_C, 2 * IN_C + ECH);
    k_gemm<<<ggrid, 256>>>(W1, b1, 2 * IN_C + ECH);
    k_stats<<<STATS_BLOCKS, HID>>>();
    k_finalize<<<1, HID>>>(g1, be1);
    k_norm<<<norm_grid, 256>>>();

    // layer 2 (D=256, K=576)
    k_agg<<<NN, HID>>>(nullptr, HID, 2 * HID + ECH);
    k_gemm<<<ggrid, 256>>>(W2, b2, 2 * HID + ECH);
    k_stats<<<STATS_BLOCKS, HID>>>();
    k_finalize<<<1, HID>>>(g2, be2);
    k_norm<<<norm_grid, 256>>>();

    // layer 3 (D=256, K=576)
    k_agg<<<NN, HID>>>(nullptr, HID, 2 * HID + ECH);
    k_gemm<<<ggrid, 256>>>(W3, b3, 2 * HID + ECH);
    k_stats<<<STATS_BLOCKS, HID>>>();
    k_finalize<<<1, HID>>>(g3, be3);
    k_norm<<<norm_grid, 256>>>();

    // readout
    k_pool<<<BB, HID>>>(neighbor);
    k_fc1<<<BB, MLPD>>>(fc1w, fc1b);
    k_fc2<<<BB, 128>>>(fc2w, fc2b, out);
}

// round 4
// speedup vs baseline: 1.4511x; 1.4511x over previous
#include <cuda_runtime.h>
#include <cuda_bf16.h>
#include <cstdint>

// Problem constants
#define NN   10000
#define EE   320000
#define BB   64
#define IN_C 128
#define ECH  64
#define HID  256
#define MLPD 512
#define NCL  4
#define KMAX 576          // 2*HID + ECH
#define STATS_BLOCKS 40
#define ROWS_PER_STAT 250

// GEMM tiling
#define BM 64
#define BN 128
#define BK 32
#define ASTR 80           // smem row stride in bytes (64B data + 16B pad)

// ---------------- scratch (static device globals; no allocation) -------------
__device__ __nv_bfloat16 g_Xhi[NN * KMAX];
__device__ __nv_bfloat16 g_Xlo[NN * KMAX];
__device__ __nv_bfloat16 g_Wthi[HID * KMAX];   // W transposed: [n][k]
__device__ __nv_bfloat16 g_Wtlo[HID * KMAX];
__device__ float g_pre[NN * HID];      // GEMM output (relu'd)
__device__ float g_h[NN * HID];        // layer output
__device__ float g_aggea[NN * ECH];
__device__ float g_deg[NN];
__device__ int   g_indeg[NN];
__device__ int   g_off[NN + 1];
__device__ int   g_pos[NN];
__device__ int   g_csrc[EE];
__device__ int   g_ceid[EE];
__device__ float g_ps[STATS_BLOCKS * HID];
__device__ float g_pq[STATS_BLOCKS * HID];
__device__ float g_scale[HID];
__device__ float g_shift[HID];
__device__ int   g_bcnt[BB];
__device__ int   g_boff[BB];
__device__ float g_z[BB * (HID + 1 + IN_C)];
__device__ float g_fc1[BB * MLPD];

// ---------------- helpers ----------------------------------------------------
__device__ __forceinline__ uint32_t smem_u32(const void* p) {
    uint32_t a;
    asm("{ .reg .u64 t; cvta.to.shared.u64 t, %1; cvt.u32.u64 %0, t; }" : "=r"(a) : "l"(p));
    return a;
}
__device__ __forceinline__ void ldm_x4(uint32_t* r, uint32_t addr) {
    asm volatile("ldmatrix.sync.aligned.m8n8.x4.shared.b16 {%0,%1,%2,%3}, [%4];"
                 : "=r"(r[0]), "=r"(r[1]), "=r"(r[2]), "=r"(r[3]) : "r"(addr));
}
__device__ __forceinline__ void mma_bf16(float* d, const uint32_t* a, const uint32_t* b) {
    asm volatile("mma.sync.aligned.m16n8k16.row.col.f32.bf16.bf16.f32 "
                 "{%0,%1,%2,%3}, {%4,%5,%6,%7}, {%8,%9}, {%0,%1,%2,%3};"
                 : "+f"(d[0]), "+f"(d[1]), "+f"(d[2]), "+f"(d[3])
                 : "r"(a[0]), "r"(a[1]), "r"(a[2]), "r"(a[3]), "r"(b[0]), "r"(b[1]));
}
__device__ __forceinline__ void split_bf16(float x, __nv_bfloat16& hi, __nv_bfloat16& lo) {
    hi = __float2bfloat16_rn(x);
    lo = __float2bfloat16_rn(x - __bfloat162float(hi));
}

// ---------------- setup kernels ---------------------------------------------
__global__ void k_zero() {
    int i = blockIdx.x * blockDim.x + threadIdx.x;
    if (i < NN) g_indeg[i] = 0;
    if (i < BB) g_bcnt[i] = 0;
}

__global__ void k_hist(const int* __restrict__ dst, const int* __restrict__ batch) {
    int i = blockIdx.x * blockDim.x + threadIdx.x;
    if (i < EE) atomicAdd(&g_indeg[dst[i]], 1);
    if (i < NN) atomicAdd(&g_bcnt[batch[i]], 1);
}

// single-block scan over indeg (N=10000), shuffle-based, one pass
__global__ void k_scan() {
    __shared__ int wsum[32];
    int t = threadIdx.x;               // 1024
    int lane = t & 31, wd = t >> 5;
    int vals[10];
    int s = 0;
    int base = t * 10;
#pragma unroll
    for (int i = 0; i < 10; i++) {
        int idx = base + i;
        int v = (idx < NN) ? g_indeg[idx] : 0;
        vals[i] = v;
        s += v;
    }
    int inc = s;
#pragma unroll
    for (int o = 1; o < 32; o <<= 1) {
        int n = __shfl_up_sync(0xFFFFFFFF, inc, o);
        if (lane >= o) inc += n;
    }
    if (lane == 31) wsum[wd] = inc;
    __syncthreads();
    if (wd == 0) {
        int x = wsum[lane];
#pragma unroll
        for (int o = 1; o < 32; o <<= 1) {
            int n = __shfl_up_sync(0xFFFFFFFF, x, o);
            if (lane >= o) x += n;
        }
        wsum[lane] = x;
    }
    __syncthreads();
    int off = inc - s + (wd ? wsum[wd - 1] : 0);
#pragma unroll
    for (int i = 0; i < 10; i++) {
        int idx = base + i;
        if (idx < NN) {
            g_off[idx] = off;
            g_pos[idx] = off;
            g_deg[idx] = (float)(vals[i] + 1);
        }
        off += vals[i];
    }
    if (t == 0) {
        g_off[NN] = EE;
        int c = 0;
        for (int b = 0; b < BB; b++) { g_boff[b] = c; c += g_bcnt[b]; }
    }
}

__global__ void k_fill(const int* __restrict__ src, const int* __restrict__ dst) {
    int e = blockIdx.x * blockDim.x + threadIdx.x;
    if (e >= EE) return;
    int d = dst[e];
    int p = atomicAdd(&g_pos[d], 1);
    g_csrc[p] = src[e];
    g_ceid[p] = e;
}

__global__ void k_aggea(const float* __restrict__ ea) {
    int v = blockIdx.x, t = threadIdx.x;  // blockDim = 64
    int s0 = g_off[v], s1 = g_off[v + 1];
    float acc = 1.0f;
    for (int j = s0; j < s1; j++) acc += ea[(size_t)g_ceid[j] * ECH + t];
    g_aggea[v * ECH + t] = acc;
}

// W [K,256] -> transposed split bf16 [256][K]
__global__ void k_wprep(const float* __restrict__ W, int K) {
    int i = blockIdx.x * blockDim.x + threadIdx.x;
    if (i >= K * HID) return;
    int k = i >> 8, n = i & (HID - 1);
    __nv_bfloat16 hi, lo;
    split_bf16(W[i], hi, lo);
    g_Wthi[(size_t)n * K + k] = hi;
    g_Wtlo[(size_t)n * K + k] = lo;
}

// ---------------- per-layer kernels -----------------------------------------
// Build split-bf16 X[v,:] = [ deg[v]*h[v,:](D) | sum_in h[src,:](D) | agg_ea(64) ]
__global__ void k_agg(const float* __restrict__ hx, int D, int Kc) {
    const float* h = hx ? hx : g_h;
    int v = blockIdx.x, t = threadIdx.x;   // blockDim = D
    int s0 = g_off[v], s1 = g_off[v + 1];
    float hv = h[(size_t)v * D + t];
    float acc = hv;
    for (int j = s0; j < s1; j++) acc += h[(size_t)g_csrc[j] * D + t];

    __nv_bfloat16* Xh = g_Xhi + (size_t)v * Kc;
    __nv_bfloat16* Xl = g_Xlo + (size_t)v * Kc;
    __nv_bfloat16 hi, lo;
    split_bf16(g_deg[v] * hv, hi, lo);
    Xh[t] = hi; Xl[t] = lo;
    split_bf16(acc, hi, lo);
    Xh[D + t] = hi; Xl[D + t] = lo;
    if (t < ECH) {
        split_bf16(g_aggea[v * ECH + t], hi, lo);
        Xh[2 * D + t] = hi; Xl[2 * D + t] = lo;
    }
}

// Warp-MMA split-bf16 GEMM: g_pre[BMxBN tile] = relu(X @ W^T + deg*bias)
// grid (ceil(NN/64), 2), 128 threads (4 warps, each 64x32).
__global__ void __launch_bounds__(128) k_gemm_mma(const float* __restrict__ bias, int K) {
    __shared__ __align__(16) uint8_t sAhi[BM * ASTR];
    __shared__ __align__(16) uint8_t sAlo[BM * ASTR];
    __shared__ __align__(16) uint8_t sBhi[BN * ASTR];
    __shared__ __align__(16) uint8_t sBlo[BN * ASTR];

    const int tid = threadIdx.x;
    const int warp = tid >> 5, lane = tid & 31;
    const int row0 = blockIdx.x * BM;
    const int n0 = blockIdx.y * BN;
    const int wn0 = warp * 32;

    const uint32_t uAhi = smem_u32(sAhi), uAlo = smem_u32(sAlo);
    const uint32_t uBhi = smem_u32(sBhi), uBlo = smem_u32(sBlo);

    float acc[4][4][4];
#pragma unroll
    for (int mi = 0; mi < 4; mi++)
#pragma unroll
        for (int ni = 0; ni < 4; ni++)
#pragma unroll
            for (int r = 0; r < 4; r++) acc[mi][ni][r] = 0.f;

    // global->smem mapping
    const int ar = tid >> 1;            // A row 0..63
    const int ahB = (tid & 1) * 32;     // byte offset within 64B row chunk
    const int am = row0 + ar;
    const bool a_ok = am < NN;
    const int bn = n0 + tid;            // B row (n) 0..255

    const int nchunks = K >> 5;
    for (int c = 0; c < nchunks; c++) {
        // ---- load A chunk (64 rows x 32 bf16, hi+lo) ----
        {
            uint4 h0 = {0,0,0,0}, h1 = {0,0,0,0}, l0 = {0,0,0,0}, l1 = {0,0,0,0};
            if (a_ok) {
                const char* ph = (const char*)g_Xhi + ((size_t)am * K + c * 32) * 2 + ahB;
                const char* pl = (const char*)g_Xlo + ((size_t)am * K + c * 32) * 2 + ahB;
                h0 = *(const uint4*)ph; h1 = *(const uint4*)(ph + 16);
                l0 = *(const uint4*)pl; l1 = *(const uint4*)(pl + 16);
            }
            *(uint4*)(sAhi + ar * ASTR + ahB)      = h0;
            *(uint4*)(sAhi + ar * ASTR + ahB + 16) = h1;
            *(uint4*)(sAlo + ar * ASTR + ahB)      = l0;
            *(uint4*)(sAlo + ar * ASTR + ahB + 16) = l1;
        }
        // ---- load B chunk (128 rows x 32 bf16, hi+lo) ----
        {
            const char* ph = (const char*)g_Wthi + ((size_t)bn * K + c * 32) * 2;
            const char* pl = (const char*)g_Wtlo + ((size_t)bn * K + c * 32) * 2;
#pragma unroll
            for (int j = 0; j < 4; j++) {
                *(uint4*)(sBhi + tid * ASTR + j * 16) = *(const uint4*)(ph + j * 16);
                *(uint4*)(sBlo + tid * ASTR + j * 16) = *(const uint4*)(pl + j * 16);
            }
        }
        __syncthreads();

#pragma unroll
        for (int kt = 0; kt < 2; kt++) {
            const uint32_t aoff = (uint32_t)((kt * 32) + ((lane >> 4) * 16));
            uint32_t ah[4][4], al[4][4];
#pragma unroll
            for (int mi = 0; mi < 4; mi++) {
                uint32_t ra = (uint32_t)((mi * 16 + (lane & 15)) * ASTR) + aoff;
                ldm_x4(ah[mi], uAhi + ra);
                ldm_x4(al[mi], uAlo + ra);
            }
            uint32_t bh[8], bl[8];
#pragma unroll
            for (int bj = 0; bj < 2; bj++) {
                int nrow = wn0 + (bj * 2 + (lane >> 4)) * 8 + (lane & 7);
                uint32_t rb = (uint32_t)(nrow * ASTR) + (uint32_t)(kt * 32 + ((lane >> 3) & 1) * 16);
                ldm_x4(&bh[bj * 4], uBhi + rb);
                ldm_x4(&bl[bj * 4], uBlo + rb);
            }
#pragma unroll
            for (int mi = 0; mi < 4; mi++)
#pragma unroll
                for (int ni = 0; ni < 4; ni++) {
                    mma_bf16(acc[mi][ni], ah[mi], &bh[ni * 2]);
                    mma_bf16(acc[mi][ni], al[mi], &bh[ni * 2]);
                    mma_bf16(acc[mi][ni], ah[mi], &bl[ni * 2]);
                }
        }
        __syncthreads();
    }

    // ---- epilogue: relu(acc + deg*bias) ----
    const int rsub = lane >> 2;
    const int cpair = (lane & 3) * 2;
#pragma unroll
    for (int mi = 0; mi < 4; mi++) {
        int m0 = row0 + mi * 16 + rsub;
        int m1 = m0 + 8;
        float dg0 = (m0 < NN) ? g_deg[m0] : 0.f;
        float dg1 = (m1 < NN) ? g_deg[m1] : 0.f;
#pragma unroll
        for (int ni = 0; ni < 4; ni++) {
            int col = n0 + wn0 + ni * 8 + cpair;
            float2 bb = *(const float2*)&bias[col];
            if (m0 < NN) {
                float2 o;
                o.x = fmaxf(acc[mi][ni][0] + dg0 * bb.x, 0.f);
                o.y = fmaxf(acc[mi][ni][1] + dg0 * bb.y, 0.f);
                *(float2*)&g_pre[(size_t)m0 * HID + col] = o;
            }
            if (m1 < NN) {
                float2 o;
                o.x = fmaxf(acc[mi][ni][2] + dg1 * bb.x, 0.f);
                o.y = fmaxf(acc[mi][ni][3] + dg1 * bb.y, 0.f);
                *(float2*)&g_pre[(size_t)m1 * HID + col] = o;
            }
        }
    }
}

// per-channel partial sum / sumsq (g_pre already relu'd)
__global__ void k_stats() {
    int t = threadIdx.x;           // 256
    int b = blockIdx.x;            // 40
    int r0 = b * ROWS_PER_STAT;
    int r1 = r0 + ROWS_PER_STAT;
    float s = 0.f, q = 0.f;
    for (int r = r0; r < r1; r++) {
        float v = g_pre[(size_t)r * HID + t];
        s += v;
        q += v * v;
    }
    g_ps[b * HID + t] = s;
    g_pq[b * HID + t] = q;
}

__global__ void k_finalize(const float* __restrict__ gamma, const float* __restrict__ beta) {
    int t = threadIdx.x;  // 256
    float s = 0.f, q = 0.f;
    for (int b = 0; b < STATS_BLOCKS; b++) {
        s += g_ps[b * HID + t];
        q += g_pq[b * HID + t];
    }
    float inv_n = 1.0f / (float)NN;
    float mu = s * inv_n;
    float var = q * inv_n - mu * mu;
    float rs = rsqrtf(var + 1e-5f);
    float sc = rs * gamma[t];
    g_scale[t] = sc;
    g_shift[t] = beta[t] - mu * sc;
}

__global__ void k_norm() {
    int i = blockIdx.x * blockDim.x + threadIdx.x;
    if (i >= NN * HID) return;
    int c = i & (HID - 1);
    g_h[i] = fmaxf(g_pre[i] * g_scale[c] + g_shift[c], 0.f);
}

// ---------------- readout ---------------------------------------------------
__global__ void k_pool(const float* __restrict__ neighbor) {
    int b = blockIdx.x, t = threadIdx.x;   // 256
    int s0 = g_boff[b], c = g_bcnt[b];
    float acc = 0.f;
    for (int r = 0; r < c; r++) acc += g_h[(size_t)(s0 + r) * HID + t];
    float* zr = g_z + (size_t)b * (HID + 1 + IN_C);
    zr[t] = acc;
    if (t == 0) zr[HID] = (float)c / 40.0f;
    if (t < IN_C) zr[HID + 1 + t] = neighbor[b * IN_C + t];
}

__global__ void k_fc1(const float* __restrict__ w, const float* __restrict__ bias) {
    __shared__ float zs[HID + 1 + IN_C];   // 385
    int b = blockIdx.x, t = threadIdx.x;   // 512
    if (t < HID + 1 + IN_C) zs[t] = g_z[(size_t)b * (HID + 1 + IN_C) + t];
    __syncthreads();
    float acc = bias[t];
    for (int k = 0; k < HID + 1 + IN_C; k++) acc = fmaf(zs[k], w[(size_t)k * MLPD + t], acc);
    g_fc1[(size_t)b * MLPD + t] = fmaxf(acc, 0.f);
}

__global__ void k_fc2(const float* __restrict__ w, const float* __restrict__ bias,
                      float* __restrict__ out) {
    int b = blockIdx.x;
    int t = threadIdx.x;           // 128
    int wrp = t >> 5;
    int lane = t & 31;
    float acc = 0.f;
    for (int k = lane; k < MLPD; k += 32)
        acc = fmaf(g_fc1[(size_t)b * MLPD + k], w[(size_t)k * NCL + wrp], acc);
#pragma unroll
    for (int o = 16; o > 0; o >>= 1) acc += __shfl_down_sync(0xFFFFFFFF, acc, o);
    if (lane == 0) out[b * NCL + wrp] = acc + bias[wrp];
}

// ---------------- launch -----------------------------------------------------
extern "C" void kernel_launch(void* const* d_in, const int* in_sizes, int n_in,
                              void* d_out, int out_size) {
    const float* x        = (const float*)d_in[0];
    const int*   ei       = (const int*)d_in[1];
    const float* ea       = (const float*)d_in[2];
    const int*   batch    = (const int*)d_in[3];
    const float* neighbor = (const float*)d_in[4];
    const float* W1  = (const float*)d_in[5];
    const float* b1  = (const float*)d_in[6];
    const float* g1  = (const float*)d_in[7];
    const float* be1 = (const float*)d_in[8];
    const float* W2  = (const float*)d_in[9];
    const float* b2  = (const float*)d_in[10];
    const float* g2  = (const float*)d_in[11];
    const float* be2 = (const float*)d_in[12];
    const float* W3  = (const float*)d_in[13];
    const float* b3  = (const float*)d_in[14];
    const float* g3  = (const float*)d_in[15];
    const float* be3 = (const float*)d_in[16];
    const float* fc1w = (const float*)d_in[17];
    const float* fc1b = (const float*)d_in[18];
    const float* fc2w = (const float*)d_in[19];
    const float* fc2b = (const float*)d_in[20];
    float* out = (float*)d_out;

    const int* src = ei;
    const int* dst = ei + EE;

    // CSR + degrees + batch offsets + edge-attr aggregation
    k_zero<<<(NN + 255) / 256, 256>>>();
    k_hist<<<(EE + 255) / 256, 256>>>(dst, batch);
    k_scan<<<1, 1024>>>();
    k_fill<<<(EE + 255) / 256, 256>>>(src, dst);
    k_aggea<<<NN, ECH>>>(ea);

    dim3 ggrid((NN + BM - 1) / BM, HID / BN);
    int norm_grid = (NN * HID + 255) / 256;
    int K1 = 2 * IN_C + ECH;   // 320
    int K23 = 2 * HID + ECH;   // 576

    // layer 1
    k_wprep<<<(K1 * HID + 255) / 256, 256>>>(W1, K1);
    k_agg<<<NN, IN_C>>>(x, IN_C, K1);
    k_gemm_mma<<<ggrid, 128>>>(b1, K1);
    k_stats<<<STATS_BLOCKS, HID>>>();
    k_finalize<<<1, HID>>>(g1, be1);
    k_norm<<<norm_grid, 256>>>();

    // layer 2
    k_wprep<<<(K23 * HID + 255) / 256, 256>>>(W2, K23);
    k_agg<<<NN, HID>>>(nullptr, HID, K23);
    k_gemm_mma<<<ggrid, 128>>>(b2, K23);
    k_stats<<<STATS_BLOCKS, HID>>>();
    k_finalize<<<1, HID>>>(g2, be2);
    k_norm<<<norm_grid, 256>>>();

    // layer 3
    k_wprep<<<(K23 * HID + 255) / 256, 256>>>(W3, K23);
    k_agg<<<NN, HID>>>(nullptr, HID, K23);
    k_gemm_mma<<<ggrid, 128>>>(b3, K23);
    k_stats<<<STATS_BLOCKS, HID>>>();
    k_finalize<<<1, HID>>>(g3, be3);
    k_norm<<<norm_grid, 256>>>();

    // readout
    k_pool<<<BB, HID>>>(neighbor);
    k_fc1<<<BB, MLPD>>>(fc1w, fc1b);
    k_fc2<<<BB, 128>>>(fc2w, fc2b, out);
}

// round 6
// speedup vs baseline: 1.8096x; 1.2471x over previous
#include <cuda_runtime.h>
#include <cuda_bf16.h>
#include <cstdint>

// Problem constants
#define NN   10000
#define EE   320000
#define BB   64
#define IN_C 128
#define ECH  64
#define HID  256
#define MLPD 512
#define NCL  4
#define KMAX 576
#define ZDIM (HID + 1 + IN_C)   // 385

// GEMM tiling
#define BM 64
#define BN 128
#define ASTR 80

// ---------------- scratch ----------------------------------------------------
__device__ __align__(16) __nv_bfloat16 g_Xhi[NN * KMAX];
__device__ __align__(16) __nv_bfloat16 g_Xlo[NN * KMAX];
__device__ __align__(16) __nv_bfloat16 g_Wthi[3 * HID * KMAX];
__device__ __align__(16) __nv_bfloat16 g_Wtlo[3 * HID * KMAX];
__device__ __align__(16) float g_pre[NN * HID];
__device__ __align__(16) float g_aggea[NN * ECH];
__device__ float g_deg[NN];
__device__ int   g_indeg[NN];
__device__ int   g_off[NN + 1];
__device__ int   g_pos[NN];
__device__ int   g_csrc[EE];
__device__ int   g_ceid[EE];
__device__ float g_statsA[2 * HID];   // [0:256) sum, [256:512) sumsq
__device__ float g_statsB[2 * HID];
__device__ int   g_bcnt[BB];
__device__ int   g_boff[BB];

// ---------------- helpers ----------------------------------------------------
__device__ __forceinline__ uint32_t smem_u32(const void* p) {
    uint32_t a;
    asm("{ .reg .u64 t; cvta.to.shared.u64 t, %1; cvt.u32.u64 %0, t; }" : "=r"(a) : "l"(p));
    return a;
}
__device__ __forceinline__ void ldm_x4(uint32_t* r, uint32_t addr) {
    asm volatile("ldmatrix.sync.aligned.m8n8.x4.shared.b16 {%0,%1,%2,%3}, [%4];"
                 : "=r"(r[0]), "=r"(r[1]), "=r"(r[2]), "=r"(r[3]) : "r"(addr));
}
__device__ __forceinline__ void mma_bf16(float* d, const uint32_t* a, const uint32_t* b) {
    asm volatile("mma.sync.aligned.m16n8k16.row.col.f32.bf16.bf16.f32 "
                 "{%0,%1,%2,%3}, {%4,%5,%6,%7}, {%8,%9}, {%0,%1,%2,%3};"
                 : "+f"(d[0]), "+f"(d[1]), "+f"(d[2]), "+f"(d[3])
                 : "r"(a[0]), "r"(a[1]), "r"(a[2]), "r"(a[3]), "r"(b[0]), "r"(b[1]));
}
__device__ __forceinline__ unsigned short bfu(__nv_bfloat16 h) {
    return *reinterpret_cast<unsigned short*>(&h);
}
__device__ __forceinline__ void split1(float x, unsigned short& h, unsigned short& l) {
    __nv_bfloat16 hi = __float2bfloat16_rn(x);
    __nv_bfloat16 lo = __float2bfloat16_rn(x - __bfloat162float(hi));
    h = bfu(hi); l = bfu(lo);
}
__device__ __forceinline__ void split4_store(float4 v, __nv_bfloat16* Xh, __nv_bfloat16* Xl,
                                             size_t off) {
    unsigned short h0, l0, h1, l1, h2, l2, h3, l3;
    split1(v.x, h0, l0); split1(v.y, h1, l1); split1(v.z, h2, l2); split1(v.w, h3, l3);
    uint2 uh, ul;
    uh.x = (uint32_t)h0 | ((uint32_t)h1 << 16);
    uh.y = (uint32_t)h2 | ((uint32_t)h3 << 16);
    ul.x = (uint32_t)l0 | ((uint32_t)l1 << 16);
    ul.y = (uint32_t)l2 | ((uint32_t)l3 << 16);
    *(uint2*)(Xh + off) = uh;
    *(uint2*)(Xl + off) = ul;
}

// ---------------- setup kernels ---------------------------------------------
__global__ void k_zero() {
    int i = blockIdx.x * blockDim.x + threadIdx.x;
    if (i < NN) g_indeg[i] = 0;
    if (i < BB) g_bcnt[i] = 0;
}

__global__ void k_hist(const int* __restrict__ dst, const int* __restrict__ batch) {
    int i = blockIdx.x * blockDim.x + threadIdx.x;
    if (i < EE) atomicAdd(&g_indeg[dst[i]], 1);
    if (i < NN) atomicAdd(&g_bcnt[batch[i]], 1);
}

__global__ void k_scan() {
    __shared__ int wsum[32];
    int t = threadIdx.x;               // 1024
    int lane = t & 31, wd = t >> 5;
    int vals[10];
    int s = 0;
    int base = t * 10;
#pragma unroll
    for (int i = 0; i < 10; i++) {
        int idx = base + i;
        int v = (idx < NN) ? g_indeg[idx] : 0;
        vals[i] = v;
        s += v;
    }
    int inc = s;
#pragma unroll
    for (int o = 1; o < 32; o <<= 1) {
        int n = __shfl_up_sync(0xFFFFFFFF, inc, o);
        if (lane >= o) inc += n;
    }
    if (lane == 31) wsum[wd] = inc;
    __syncthreads();
    if (wd == 0) {
        int x = wsum[lane];
#pragma unroll
        for (int o = 1; o < 32; o <<= 1) {
            int n = __shfl_up_sync(0xFFFFFFFF, x, o);
            if (lane >= o) x += n;
        }
        wsum[lane] = x;
    }
    __syncthreads();
    int off = inc - s + (wd ? wsum[wd - 1] : 0);
#pragma unroll
    for (int i = 0; i < 10; i++) {
        int idx = base + i;
        if (idx < NN) {
            g_off[idx] = off;
            g_pos[idx] = off;
            g_deg[idx] = (float)(vals[i] + 1);
        }
        off += vals[i];
    }
    if (t == 0) {
        g_off[NN] = EE;
        int c = 0;
        for (int b = 0; b < BB; b++) { g_boff[b] = c; c += g_bcnt[b]; }
    }
}

__global__ void k_fill(const int* __restrict__ src, const int* __restrict__ dst) {
    int e = blockIdx.x * blockDim.x + threadIdx.x;
    if (e >= EE) return;
    int d = dst[e];
    int p = atomicAdd(&g_pos[d], 1);
    g_csrc[p] = src[e];
    g_ceid[p] = e;
}

// per-node sum of incoming edge_attr + self-loop 1.0 (float4, 8 nodes/block)
__global__ void k_aggea(const float* __restrict__ ea) {
    int tid = threadIdx.x;             // 128
    int node = blockIdx.x * 8 + (tid >> 4);
    int q = (tid & 15) * 4;
    int s0 = g_off[node], s1 = g_off[node + 1];
    float4 acc = make_float4(1.f, 1.f, 1.f, 1.f);
#pragma unroll 2
    for (int j = s0; j < s1; j++) {
        float4 u = *(const float4*)&ea[(size_t)g_ceid[j] * ECH + q];
        acc.x += u.x; acc.y += u.y; acc.z += u.z; acc.w += u.w;
    }
    *(float4*)&g_aggea[node * ECH + q] = acc;
}

// All 3 weight matrices [K,256] -> transposed split bf16 [layer][n][k]
__global__ void k_wprep_all(const float* __restrict__ W1, const float* __restrict__ W2,
                            const float* __restrict__ W3) {
    int layer = blockIdx.y;
    const float* W = (layer == 0) ? W1 : (layer == 1 ? W2 : W3);
    int K = (layer == 0) ? 320 : 576;
    int i = blockIdx.x * 256 + threadIdx.x;
    if (i >= K * HID) return;
    int k = i >> 8, n = i & (HID - 1);
    unsigned short h, l;
    split1(W[i], h, l);
    size_t o = (size_t)layer * HID * KMAX + (size_t)n * K + k;
    *reinterpret_cast<unsigned short*>(&g_Wthi[o]) = h;
    *reinterpret_cast<unsigned short*>(&g_Wtlo[o]) = l;
}

// ---------------- aggregation (+ inline BN of previous layer) ---------------
// X[v,:] = [ deg*h | sum_in h | agg_ea ], h = BN_APPLY ? relu(bn(g_pre)) : fx
// NOTE: device-global g_pre is selected INSIDE the kernel (fx==nullptr);
// passing the __device__ symbol from host silently reads the host shadow
// via GB300 ATS (R5 bug).
template<int D, bool BN_APPLY>
__global__ void __launch_bounds__(128) k_agg_t(const float* __restrict__ fx,
                                               const float* __restrict__ gamma,
                                               const float* __restrict__ beta,
                                               const float* __restrict__ stats,
                                               float* __restrict__ zeroStats,
                                               int Kc) {
    const float* feat = fx ? fx : (const float*)g_pre;
    constexpr int T4 = D / 4;
    constexpr int NPB = 128 / T4;
    int tid = threadIdx.x;
    if (blockIdx.x == 0) {
        for (int i = tid; i < 2 * HID; i += 128) zeroStats[i] = 0.f;
    }
    int node = blockIdx.x * NPB + tid / T4;
    int t4 = tid % T4;
    int c = t4 * 4;

    float4 sc, sh;
    if (BN_APPLY) {
        const float inv_n = 1.0f / (float)NN;
#pragma unroll
        for (int j = 0; j < 4; j++) {
            float s = stats[c + j];
            float q = stats[HID + c + j];
            float mu = s * inv_n;
            float var = q * inv_n - mu * mu;
            float r = rsqrtf(var + 1e-5f);
            float scj = r * gamma[c + j];
            ((float*)&sc)[j] = scj;
            ((float*)&sh)[j] = beta[c + j] - mu * scj;
        }
    }

    int s0 = g_off[node], s1 = g_off[node + 1];
    float4 hv = *(const float4*)&feat[(size_t)node * D + c];
    if (BN_APPLY) {
        hv.x = fmaxf(fmaf(hv.x, sc.x, sh.x), 0.f);
        hv.y = fmaxf(fmaf(hv.y, sc.y, sh.y), 0.f);
        hv.z = fmaxf(fmaf(hv.z, sc.z, sh.z), 0.f);
        hv.w = fmaxf(fmaf(hv.w, sc.w, sh.w), 0.f);
    }
    float4 acc = hv;
#pragma unroll 2
    for (int j = s0; j < s1; j++) {
        int s = g_csrc[j];
        float4 u = *(const float4*)&feat[(size_t)s * D + c];
        if (BN_APPLY) {
            u.x = fmaxf(fmaf(u.x, sc.x, sh.x), 0.f);
            u.y = fmaxf(fmaf(u.y, sc.y, sh.y), 0.f);
            u.z = fmaxf(fmaf(u.z, sc.z, sh.z), 0.f);
            u.w = fmaxf(fmaf(u.w, sc.w, sh.w), 0.f);
        }
        acc.x += u.x; acc.y += u.y; acc.z += u.z; acc.w += u.w;
    }

    float dg = g_deg[node];
    float4 dv = make_float4(dg * hv.x, dg * hv.y, dg * hv.z, dg * hv.w);
    size_t rb = (size_t)node * Kc;
    split4_store(dv, g_Xhi, g_Xlo, rb + c);
    split4_store(acc, g_Xhi, g_Xlo, rb + D + c);
    if (t4 < ECH / 4) {
        float4 e4 = *(const float4*)&g_aggea[node * ECH + c];
        split4_store(e4, g_Xhi, g_Xlo, rb + 2 * D + c);
    }
}

// ---------------- GEMM (warp MMA, split bf16) + fused stats ------------------
__global__ void __launch_bounds__(128) k_gemm_mma(const float* __restrict__ bias, int K,
                                                  int layer, float* __restrict__ stats) {
    __shared__ __align__(16) uint8_t sAhi[BM * ASTR];
    __shared__ __align__(16) uint8_t sAlo[BM * ASTR];
    __shared__ __align__(16) uint8_t sBhi[BN * ASTR];
    __shared__ __align__(16) uint8_t sBlo[BN * ASTR];

    const __nv_bfloat16* wtHi = g_Wthi + (size_t)layer * HID * KMAX;
    const __nv_bfloat16* wtLo = g_Wtlo + (size_t)layer * HID * KMAX;

    const int tid = threadIdx.x;
    const int warp = tid >> 5, lane = tid & 31;
    const int row0 = blockIdx.x * BM;
    const int n0 = blockIdx.y * BN;
    const int wn0 = warp * 32;

    const uint32_t uAhi = smem_u32(sAhi), uAlo = smem_u32(sAlo);
    const uint32_t uBhi = smem_u32(sBhi), uBlo = smem_u32(sBlo);

    float acc[4][4][4];
#pragma unroll
    for (int mi = 0; mi < 4; mi++)
#pragma unroll
        for (int ni = 0; ni < 4; ni++)
#pragma unroll
            for (int r = 0; r < 4; r++) acc[mi][ni][r] = 0.f;

    const int ar = tid >> 1;
    const int ahB = (tid & 1) * 32;
    const int am = row0 + ar;
    const bool a_ok = am < NN;
    const int bn = n0 + tid;

    const int nchunks = K >> 5;
    for (int c = 0; c < nchunks; c++) {
        {
            uint4 h0 = {0,0,0,0}, h1 = {0,0,0,0}, l0 = {0,0,0,0}, l1 = {0,0,0,0};
            if (a_ok) {
                const char* ph = (const char*)g_Xhi + ((size_t)am * K + c * 32) * 2 + ahB;
                const char* pl = (const char*)g_Xlo + ((size_t)am * K + c * 32) * 2 + ahB;
                h0 = *(const uint4*)ph; h1 = *(const uint4*)(ph + 16);
                l0 = *(const uint4*)pl; l1 = *(const uint4*)(pl + 16);
            }
            *(uint4*)(sAhi + ar * ASTR + ahB)      = h0;
            *(uint4*)(sAhi + ar * ASTR + ahB + 16) = h1;
            *(uint4*)(sAlo + ar * ASTR + ahB)      = l0;
            *(uint4*)(sAlo + ar * ASTR + ahB + 16) = l1;
        }
        {
            const char* ph = (const char*)wtHi + ((size_t)bn * K + c * 32) * 2;
            const char* pl = (const char*)wtLo + ((size_t)bn * K + c * 32) * 2;
#pragma unroll
            for (int j = 0; j < 4; j++) {
                *(uint4*)(sBhi + tid * ASTR + j * 16) = *(const uint4*)(ph + j * 16);
                *(uint4*)(sBlo + tid * ASTR + j * 16) = *(const uint4*)(pl + j * 16);
            }
        }
        __syncthreads();

#pragma unroll
        for (int kt = 0; kt < 2; kt++) {
            const uint32_t aoff = (uint32_t)((kt * 32) + ((lane >> 4) * 16));
            uint32_t ah[4][4], al[4][4];
#pragma unroll
            for (int mi = 0; mi < 4; mi++) {
                uint32_t ra = (uint32_t)((mi * 16 + (lane & 15)) * ASTR) + aoff;
                ldm_x4(ah[mi], uAhi + ra);
                ldm_x4(al[mi], uAlo + ra);
            }
            uint32_t bh[8], bl[8];
#pragma unroll
            for (int bj = 0; bj < 2; bj++) {
                int nrow = wn0 + (bj * 2 + (lane >> 4)) * 8 + (lane & 7);
                uint32_t rb = (uint32_t)(nrow * ASTR) + (uint32_t)(kt * 32 + ((lane >> 3) & 1) * 16);
                ldm_x4(&bh[bj * 4], uBhi + rb);
                ldm_x4(&bl[bj * 4], uBlo + rb);
            }
#pragma unroll
            for (int mi = 0; mi < 4; mi++)
#pragma unroll
                for (int ni = 0; ni < 4; ni++) {
                    mma_bf16(acc[mi][ni], ah[mi], &bh[ni * 2]);
                    mma_bf16(acc[mi][ni], al[mi], &bh[ni * 2]);
                    mma_bf16(acc[mi][ni], ah[mi], &bl[ni * 2]);
                }
        }
        __syncthreads();
    }

    // ---- epilogue: relu(acc + deg*bias) + column stats ----
    const int rsub = lane >> 2;
    const int cpair = (lane & 3) * 2;
    float cs[4][2], cq[4][2];
#pragma unroll
    for (int ni = 0; ni < 4; ni++) { cs[ni][0] = cs[ni][1] = cq[ni][0] = cq[ni][1] = 0.f; }

#pragma unroll
    for (int mi = 0; mi < 4; mi++) {
        int m0 = row0 + mi * 16 + rsub;
        int m1 = m0 + 8;
        float dg0 = (m0 < NN) ? g_deg[m0] : 0.f;
        float dg1 = (m1 < NN) ? g_deg[m1] : 0.f;
#pragma unroll
        for (int ni = 0; ni < 4; ni++) {
            int col = n0 + wn0 + ni * 8 + cpair;
            float2 bb = *(const float2*)&bias[col];
            if (m0 < NN) {
                float ox = fmaxf(acc[mi][ni][0] + dg0 * bb.x, 0.f);
                float oy = fmaxf(acc[mi][ni][1] + dg0 * bb.y, 0.f);
                float2 o = {ox, oy};
                *(float2*)&g_pre[(size_t)m0 * HID + col] = o;
                cs[ni][0] += ox; cq[ni][0] += ox * ox;
                cs[ni][1] += oy; cq[ni][1] += oy * oy;
            }
            if (m1 < NN) {
                float ox = fmaxf(acc[mi][ni][2] + dg1 * bb.x, 0.f);
                float oy = fmaxf(acc[mi][ni][3] + dg1 * bb.y, 0.f);
                float2 o = {ox, oy};
                *(float2*)&g_pre[(size_t)m1 * HID + col] = o;
                cs[ni][0] += ox; cq[ni][0] += ox * ox;
                cs[ni][1] += oy; cq[ni][1] += oy * oy;
            }
        }
    }
#pragma unroll
    for (int ni = 0; ni < 4; ni++) {
        float s0 = cs[ni][0], s1v = cs[ni][1], q0 = cq[ni][0], q1 = cq[ni][1];
#pragma unroll
        for (int off = 16; off >= 4; off >>= 1) {
            s0  += __shfl_down_sync(0xFFFFFFFF, s0, off);
            s1v += __shfl_down_sync(0xFFFFFFFF, s1v, off);
            q0  += __shfl_down_sync(0xFFFFFFFF, q0, off);
            q1  += __shfl_down_sync(0xFFFFFFFF, q1, off);
        }
        if (lane < 4) {
            int col = n0 + wn0 + ni * 8 + lane * 2;
            atomicAdd(&stats[col], s0);
            atomicAdd(&stats[col + 1], s1v);
            atomicAdd(&stats[HID + col], q0);
            atomicAdd(&stats[HID + col + 1], q1);
        }
    }
}

// ---------------- fused readout: pool(+BN) -> fc1 -> fc2 ---------------------
__global__ void __launch_bounds__(512) k_poolfc(const float* __restrict__ stats,
                                                const float* __restrict__ gamma,
                                                const float* __restrict__ beta,
                                                const float* __restrict__ neighbor,
                                                const float* __restrict__ fc1w,
                                                const float* __restrict__ fc1b,
                                                const float* __restrict__ fc2w,
                                                const float* __restrict__ fc2b,
                                                float* __restrict__ out) {
    __shared__ float zs[ZDIM];
    __shared__ float s1[MLPD];
    int b = blockIdx.x, t = threadIdx.x;
    int boff = g_boff[b], cnt = g_bcnt[b];

    if (t < HID) {
        const float inv_n = 1.0f / (float)NN;
        float s = stats[t], q = stats[HID + t];
        float mu = s * inv_n;
        float var = q * inv_n - mu * mu;
        float r = rsqrtf(var + 1e-5f);
        float sc = r * gamma[t];
        float sh = beta[t] - mu * sc;
        float accp = 0.f;
        for (int rr = 0; rr < cnt; rr++) {
            float v = g_pre[(size_t)(boff + rr) * HID + t];
            accp += fmaxf(fmaf(v, sc, sh), 0.f);
        }
        zs[t] = accp;
    } else if (t == HID) {
        zs[HID] = (float)cnt / 40.0f;
    } else if (t < HID + 1 + IN_C + 1 && t >= HID + 1) {
        int j = t - (HID + 1);
        if (j < IN_C) zs[HID + 1 + j] = neighbor[b * IN_C + j];
    }
    __syncthreads();

    float acc = fc1b[t];
    for (int k = 0; k < ZDIM; k++) acc = fmaf(zs[k], fc1w[(size_t)k * MLPD + t], acc);
    s1[t] = fmaxf(acc, 0.f);
    __syncthreads();

    if (t < 128) {
        int wrp = t >> 5, lane = t & 31;
        float a2 = 0.f;
        for (int k = lane; k < MLPD; k += 32)
            a2 = fmaf(s1[k], fc2w[(size_t)k * NCL + wrp], a2);
#pragma unroll
        for (int o = 16; o > 0; o >>= 1) a2 += __shfl_down_sync(0xFFFFFFFF, a2, o);
        if (lane == 0) out[b * NCL + wrp] = a2 + fc2b[wrp];
    }
}

// ---------------- launch -----------------------------------------------------
extern "C" void kernel_launch(void* const* d_in, const int* in_sizes, int n_in,
                              void* d_out, int out_size) {
    const float* x        = (const float*)d_in[0];
    const int*   ei       = (const int*)d_in[1];
    const float* ea       = (const float*)d_in[2];
    const int*   batch    = (const int*)d_in[3];
    const float* neighbor = (const float*)d_in[4];
    const float* W1  = (const float*)d_in[5];
    const float* b1  = (const float*)d_in[6];
    const float* g1  = (const float*)d_in[7];
    const float* be1 = (const float*)d_in[8];
    const float* W2  = (const float*)d_in[9];
    const float* b2  = (const float*)d_in[10];
    const float* g2  = (const float*)d_in[11];
    const float* be2 = (const float*)d_in[12];
    const float* W3  = (const float*)d_in[13];
    const float* b3  = (const float*)d_in[14];
    const float* g3  = (const float*)d_in[15];
    const float* be3 = (const float*)d_in[16];
    const float* fc1w = (const float*)d_in[17];
    const float* fc1b = (const float*)d_in[18];
    const float* fc2w = (const float*)d_in[19];
    const float* fc2b = (const float*)d_in[20];
    float* out = (float*)d_out;

    const int* src = ei;
    const int* dst = ei + EE;

    // device symbol addresses (correct API; raw symbol use from host is the R5 bug)
    float* statsA; float* statsB;
    cudaGetSymbolAddress((void**)&statsA, g_statsA);
    cudaGetSymbolAddress((void**)&statsB, g_statsB);

    // setup
    k_zero<<<(NN + 255) / 256, 256>>>();
    k_hist<<<(EE + 255) / 256, 256>>>(dst, batch);
    k_scan<<<1, 1024>>>();
    k_fill<<<(EE + 255) / 256, 256>>>(src, dst);
    k_aggea<<<NN / 8, 128>>>(ea);
    k_wprep_all<<<dim3((KMAX * HID + 255) / 256, 3), 256>>>(W1, W2, W3);

    dim3 ggrid((NN + BM - 1) / BM, HID / BN);
    int K1 = 2 * IN_C + ECH;   // 320
    int K23 = 2 * HID + ECH;   // 576

    // layer 1: input x, no BN
    k_agg_t<IN_C, false><<<NN / 4, 128>>>(x, nullptr, nullptr, nullptr, statsA, K1);
    k_gemm_mma<<<ggrid, 128>>>(b1, K1, 0, statsA);

    // layer 2: BN(layer1) inline, feat = g_pre selected device-side
    k_agg_t<HID, true><<<NN / 2, 128>>>(nullptr, g1, be1, statsA, statsB, K23);
    k_gemm_mma<<<ggrid, 128>>>(b2, K23, 1, statsB);

    // layer 3: BN(layer2) inline
    k_agg_t<HID, true><<<NN / 2, 128>>>(nullptr, g2, be2, statsB, statsA, K23);
    k_gemm_mma<<<ggrid, 128>>>(b3, K23, 2, statsA);

    // readout
    k_poolfc<<<BB, 512>>>(statsA, g3, be3, neighbor, fc1w, fc1b, fc2w, fc2b, out);
}

// round 8
// speedup vs baseline: 1.8895x; 1.0442x over previous
#include <cuda_runtime.h>
#include <cuda_bf16.h>
#include <cstdint>

// Problem constants
#define NN   10000
#define EE   320000
#define BB   64
#define IN_C 128
#define ECH  64
#define HID  256
#define MLPD 512
#define NCL  4
#define KMAX 576
#define ZDIM (HID + 1 + IN_C)   // 385

// GEMM tiling
#define BM 64
#define BN 128
#define ASTR 80
// per-buffer smem layout (bytes)
#define O_AHI 0
#define O_ALO (BM * ASTR)              // 5120
#define O_BHI (2 * BM * ASTR)          // 10240
#define O_BLO (2 * BM * ASTR + BN * ASTR) // 20480
#define BUFSZ (2 * BM * ASTR + 2 * BN * ASTR) // 30720
#define GEMM_SMEM (2 * BUFSZ)          // 61440

// ---------------- scratch ----------------------------------------------------
__device__ __align__(16) __nv_bfloat16 g_Xhi[NN * KMAX];
__device__ __align__(16) __nv_bfloat16 g_Xlo[NN * KMAX];
__device__ __align__(16) __nv_bfloat16 g_Wthi[3 * HID * KMAX];
__device__ __align__(16) __nv_bfloat16 g_Wtlo[3 * HID * KMAX];
__device__ __align__(16) float g_pre[NN * HID];
__device__ __align__(16) float g_aggea[NN * ECH];
__device__ float g_deg[NN];
__device__ int   g_indeg[NN];
__device__ int   g_off[NN + 1];
__device__ int   g_pos[NN];
__device__ int   g_csrc[EE];
__device__ int   g_ceid[EE];
__device__ float g_statsA[2 * HID];
__device__ float g_statsB[2 * HID];
__device__ int   g_bcnt[BB];
__device__ int   g_boff[BB];

// ---------------- helpers ----------------------------------------------------
__device__ __forceinline__ uint32_t smem_u32(const void* p) {
    uint32_t a;
    asm("{ .reg .u64 t; cvta.to.shared.u64 t, %1; cvt.u32.u64 %0, t; }" : "=r"(a) : "l"(p));
    return a;
}
__device__ __forceinline__ void ldm_x4(uint32_t* r, uint32_t addr) {
    asm volatile("ldmatrix.sync.aligned.m8n8.x4.shared.b16 {%0,%1,%2,%3}, [%4];"
                 : "=r"(r[0]), "=r"(r[1]), "=r"(r[2]), "=r"(r[3]) : "r"(addr));
}
__device__ __forceinline__ void mma_bf16(float* d, const uint32_t* a, const uint32_t* b) {
    asm volatile("mma.sync.aligned.m16n8k16.row.col.f32.bf16.bf16.f32 "
                 "{%0,%1,%2,%3}, {%4,%5,%6,%7}, {%8,%9}, {%0,%1,%2,%3};"
                 : "+f"(d[0]), "+f"(d[1]), "+f"(d[2]), "+f"(d[3])
                 : "r"(a[0]), "r"(a[1]), "r"(a[2]), "r"(a[3]), "r"(b[0]), "r"(b[1]));
}
__device__ __forceinline__ void cpa16(uint32_t dst, const void* src, int nbytes) {
    asm volatile("cp.async.cg.shared.global [%0], [%1], 16, %2;"
                 :: "r"(dst), "l"(src), "r"(nbytes) : "memory");
}
__device__ __forceinline__ void cpa_commit() {
    asm volatile("cp.async.commit_group;" ::: "memory");
}
__device__ __forceinline__ void cpa_wait0() {
    asm volatile("cp.async.wait_group 0;" ::: "memory");
}
__device__ __forceinline__ unsigned short bfu(__nv_bfloat16 h) {
    return *reinterpret_cast<unsigned short*>(&h);
}
__device__ __forceinline__ void split1(float x, unsigned short& h, unsigned short& l) {
    __nv_bfloat16 hi = __float2bfloat16_rn(x);
    __nv_bfloat16 lo = __float2bfloat16_rn(x - __bfloat162float(hi));
    h = bfu(hi); l = bfu(lo);
}
__device__ __forceinline__ void split4_store(float4 v, __nv_bfloat16* Xh, __nv_bfloat16* Xl,
                                             size_t off) {
    unsigned short h0, l0, h1, l1, h2, l2, h3, l3;
    split1(v.x, h0, l0); split1(v.y, h1, l1); split1(v.z, h2, l2); split1(v.w, h3, l3);
    uint2 uh, ul;
    uh.x = (uint32_t)h0 | ((uint32_t)h1 << 16);
    uh.y = (uint32_t)h2 | ((uint32_t)h3 << 16);
    ul.x = (uint32_t)l0 | ((uint32_t)l1 << 16);
    ul.y = (uint32_t)l2 | ((uint32_t)l3 << 16);
    *(uint2*)(Xh + off) = uh;
    *(uint2*)(Xl + off) = ul;
}
__device__ __forceinline__ void add4(float4& a, float4 b) {
    a.x += b.x; a.y += b.y; a.z += b.z; a.w += b.w;
}
__device__ __forceinline__ float4 bnrelu4(float4 u, float4 sc, float4 sh) {
    float4 o;
    o.x = fmaxf(fmaf(u.x, sc.x, sh.x), 0.f);
    o.y = fmaxf(fmaf(u.y, sc.y, sh.y), 0.f);
    o.z = fmaxf(fmaf(u.z, sc.z, sh.z), 0.f);
    o.w = fmaxf(fmaf(u.w, sc.w, sh.w), 0.f);
    return o;
}

// ---------------- setup kernels ---------------------------------------------
__global__ void k_zero() {
    int i = blockIdx.x * blockDim.x + threadIdx.x;
    if (i < NN) g_indeg[i] = 0;
    if (i < BB) g_bcnt[i] = 0;
}

__global__ void k_hist(const int* __restrict__ dst, const int* __restrict__ batch) {
    int i = blockIdx.x * blockDim.x + threadIdx.x;
    if (i < EE) atomicAdd(&g_indeg[dst[i]], 1);
    if (i < NN) atomicAdd(&g_bcnt[batch[i]], 1);
}

__global__ void k_scan() {
    __shared__ int wsum[32];
    int t = threadIdx.x;               // 1024
    int lane = t & 31, wd = t >> 5;
    int vals[10];
    int s = 0;
    int base = t * 10;
#pragma unroll
    for (int i = 0; i < 10; i++) {
        int idx = base + i;
        int v = (idx < NN) ? g_indeg[idx] : 0;
        vals[i] = v;
        s += v;
    }
    int inc = s;
#pragma unroll
    for (int o = 1; o < 32; o <<= 1) {
        int n = __shfl_up_sync(0xFFFFFFFF, inc, o);
        if (lane >= o) inc += n;
    }
    if (lane == 31) wsum[wd] = inc;
    __syncthreads();
    if (wd == 0) {
        int x = wsum[lane];
#pragma unroll
        for (int o = 1; o < 32; o <<= 1) {
            int n = __shfl_up_sync(0xFFFFFFFF, x, o);
            if (lane >= o) x += n;
        }
        wsum[lane] = x;
    }
    __syncthreads();
    int off = inc - s + (wd ? wsum[wd - 1] : 0);
#pragma unroll
    for (int i = 0; i < 10; i++) {
        int idx = base + i;
        if (idx < NN) {
            g_off[idx] = off;
            g_pos[idx] = off;
            g_deg[idx] = (float)(vals[i] + 1);
        }
        off += vals[i];
    }
    if (t == 0) {
        g_off[NN] = EE;
        int c = 0;
        for (int b = 0; b < BB; b++) { g_boff[b] = c; c += g_bcnt[b]; }
    }
}

__global__ void k_fill(const int* __restrict__ src, const int* __restrict__ dst) {
    int e = blockIdx.x * blockDim.x + threadIdx.x;
    if (e >= EE) return;
    int d = dst[e];
    int p = atomicAdd(&g_pos[d], 1);
    g_csrc[p] = src[e];
    g_ceid[p] = e;
}

// All 3 weight matrices [K,256] -> transposed split bf16 [layer][n][k]
__global__ void k_wprep_all(const float* __restrict__ W1, const float* __restrict__ W2,
                            const float* __restrict__ W3) {
    int layer = blockIdx.y;
    const float* W = (layer == 0) ? W1 : (layer == 1 ? W2 : W3);
    int K = (layer == 0) ? 320 : 576;
    int i = blockIdx.x * 256 + threadIdx.x;
    if (i >= K * HID) return;
    int k = i >> 8, n = i & (HID - 1);
    unsigned short h, l;
    split1(W[i], h, l);
    size_t o = (size_t)layer * HID * KMAX + (size_t)n * K + k;
    *reinterpret_cast<unsigned short*>(&g_Wthi[o]) = h;
    *reinterpret_cast<unsigned short*>(&g_Wtlo[o]) = l;
}

// ---------------- layer 1 agg: features + edge_attr fused --------------------
// X[v,:] = [ deg*x[v] | sum_in x[src] | agg_ea ]  (K=320)
__global__ void __launch_bounds__(128) k_agg1(const float* __restrict__ x,
                                              float* __restrict__ zeroStats,
                                              const float* __restrict__ ea) {
    int tid = threadIdx.x;
    if (blockIdx.x == 0) {
        for (int i = tid; i < 2 * HID; i += 128) zeroStats[i] = 0.f;
    }
    int node = blockIdx.x * 4 + (tid >> 5);
    int t4 = tid & 31;
    int c = t4 * 4;
    int s0 = g_off[node], s1 = g_off[node + 1];

    float4 hv = *(const float4*)&x[(size_t)node * IN_C + c];
    float4 acc = hv;
    float4 eacc = make_float4(1.f, 1.f, 1.f, 1.f);
    const bool do_ea = t4 < (ECH / 4);

    int j = s0;
    for (; j + 4 <= s1; j += 4) {
        int i0 = g_csrc[j], i1 = g_csrc[j + 1], i2 = g_csrc[j + 2], i3 = g_csrc[j + 3];
        float4 u0 = *(const float4*)&x[(size_t)i0 * IN_C + c];
        float4 u1 = *(const float4*)&x[(size_t)i1 * IN_C + c];
        float4 u2 = *(const float4*)&x[(size_t)i2 * IN_C + c];
        float4 u3 = *(const float4*)&x[(size_t)i3 * IN_C + c];
        if (do_ea) {
            int e0 = g_ceid[j], e1 = g_ceid[j + 1], e2 = g_ceid[j + 2], e3 = g_ceid[j + 3];
            add4(eacc, *(const float4*)&ea[(size_t)e0 * ECH + c]);
            add4(eacc, *(const float4*)&ea[(size_t)e1 * ECH + c]);
            add4(eacc, *(const float4*)&ea[(size_t)e2 * ECH + c]);
            add4(eacc, *(const float4*)&ea[(size_t)e3 * ECH + c]);
        }
        add4(acc, u0); add4(acc, u1); add4(acc, u2); add4(acc, u3);
    }
    for (; j < s1; j++) {
        int s = g_csrc[j];
        add4(acc, *(const float4*)&x[(size_t)s * IN_C + c]);
        if (do_ea) {
            int e = g_ceid[j];
            add4(eacc, *(const float4*)&ea[(size_t)e * ECH + c]);
        }
    }

    float dg = g_deg[node];
    float4 dv = make_float4(dg * hv.x, dg * hv.y, dg * hv.z, dg * hv.w);
    size_t rb = (size_t)node * 320;
    split4_store(dv, g_Xhi, g_Xlo, rb + c);
    split4_store(acc, g_Xhi, g_Xlo, rb + IN_C + c);
    if (do_ea) {
        *(float4*)&g_aggea[node * ECH + c] = eacc;
        split4_store(eacc, g_Xhi, g_Xlo, rb + 2 * IN_C + c);
    }
}

// ---------------- layers 2/3 agg with inline BN of previous layer ------------
__global__ void __launch_bounds__(128) k_agg_bn(const float* __restrict__ gamma,
                                                const float* __restrict__ beta,
                                                const float* __restrict__ stats,
                                                float* __restrict__ zeroStats) {
    const float* feat = (const float*)g_pre;
    int tid = threadIdx.x;
    if (blockIdx.x == 0) {
        for (int i = tid; i < 2 * HID; i += 128) zeroStats[i] = 0.f;
    }
    int node = blockIdx.x * 2 + (tid >> 6);
    int t4 = tid & 63;
    int c = t4 * 4;

    float4 sc, sh;
    {
        const float inv_n = 1.0f / (float)NN;
#pragma unroll
        for (int jj = 0; jj < 4; jj++) {
            float s = stats[c + jj];
            float q = stats[HID + c + jj];
            float mu = s * inv_n;
            float var = q * inv_n - mu * mu;
            float r = rsqrtf(var + 1e-5f);
            float scj = r * gamma[c + jj];
            ((float*)&sc)[jj] = scj;
            ((float*)&sh)[jj] = beta[c + jj] - mu * scj;
        }
    }

    int s0 = g_off[node], s1 = g_off[node + 1];
    float4 hv = bnrelu4(*(const float4*)&feat[(size_t)node * HID + c], sc, sh);
    float4 acc = hv;

    int j = s0;
    for (; j + 4 <= s1; j += 4) {
        int i0 = g_csrc[j], i1 = g_csrc[j + 1], i2 = g_csrc[j + 2], i3 = g_csrc[j + 3];
        float4 u0 = *(const float4*)&feat[(size_t)i0 * HID + c];
        float4 u1 = *(const float4*)&feat[(size_t)i1 * HID + c];
        float4 u2 = *(const float4*)&feat[(size_t)i2 * HID + c];
        float4 u3 = *(const float4*)&feat[(size_t)i3 * HID + c];
        add4(acc, bnrelu4(u0, sc, sh));
        add4(acc, bnrelu4(u1, sc, sh));
        add4(acc, bnrelu4(u2, sc, sh));
        add4(acc, bnrelu4(u3, sc, sh));
    }
    for (; j < s1; j++) {
        int s = g_csrc[j];
        add4(acc, bnrelu4(*(const float4*)&feat[(size_t)s * HID + c], sc, sh));
    }

    float dg = g_deg[node];
    float4 dv = make_float4(dg * hv.x, dg * hv.y, dg * hv.z, dg * hv.w);
    size_t rb = (size_t)node * 576;
    split4_store(dv, g_Xhi, g_Xlo, rb + c);
    split4_store(acc, g_Xhi, g_Xlo, rb + HID + c);
    if (t4 < ECH / 4) {
        float4 e4 = *(const float4*)&g_aggea[node * ECH + c];
        split4_store(e4, g_Xhi, g_Xlo, rb + 2 * HID + c);
    }
}

// ---------------- GEMM (warp MMA, split bf16, cp.async double buffer) --------
__global__ void __launch_bounds__(128) k_gemm_mma(const float* __restrict__ bias, int K,
                                                  int layer, float* __restrict__ stats) {
    extern __shared__ __align__(16) uint8_t dyn[];
    const uint32_t sb = smem_u32(dyn);

    const __nv_bfloat16* wtHi = g_Wthi + (size_t)layer * HID * KMAX;
    const __nv_bfloat16* wtLo = g_Wtlo + (size_t)layer * HID * KMAX;

    const int tid = threadIdx.x;
    const int warp = tid >> 5, lane = tid & 31;
    const int row0 = blockIdx.x * BM;
    const int n0 = blockIdx.y * BN;
    const int wn0 = warp * 32;

    float acc[4][4][4];
#pragma unroll
    for (int mi = 0; mi < 4; mi++)
#pragma unroll
        for (int ni = 0; ni < 4; ni++)
#pragma unroll
            for (int r = 0; r < 4; r++) acc[mi][ni][r] = 0.f;

    const int ar = tid >> 1;
    const int ahB = (tid & 1) * 32;
    const int am = row0 + ar;
    const int a_bytes = (am < NN) ? 16 : 0;
    const int am_c = (am < NN) ? am : (NN - 1);     // clamped address for zfill
    const int bn = n0 + tid;

    const char* aHiBase = (const char*)g_Xhi + ((size_t)am_c * K) * 2 + ahB;
    const char* aLoBase = (const char*)g_Xlo + ((size_t)am_c * K) * 2 + ahB;
    const char* bHiBase = (const char*)wtHi + ((size_t)bn * K) * 2;
    const char* bLoBase = (const char*)wtLo + ((size_t)bn * K) * 2;
    const uint32_t aDst = ar * ASTR + ahB;
    const uint32_t bDst = tid * ASTR;

    const int nchunks = K >> 5;

    // prefetch chunk 0 into buffer 0
    {
        const char* ph = aHiBase;
        const char* pl = aLoBase;
        cpa16(sb + O_AHI + aDst,      ph,      a_bytes);
        cpa16(sb + O_AHI + aDst + 16, ph + 16, a_bytes);
        cpa16(sb + O_ALO + aDst,      pl,      a_bytes);
        cpa16(sb + O_ALO + aDst + 16, pl + 16, a_bytes);
        const char* qh = bHiBase;
        const char* ql = bLoBase;
#pragma unroll
        for (int jj = 0; jj < 4; jj++) {
            cpa16(sb + O_BHI + bDst + jj * 16, qh + jj * 16, 16);
            cpa16(sb + O_BLO + bDst + jj * 16, ql + jj * 16, 16);
        }
        cpa_commit();
    }

    for (int c = 0; c < nchunks; c++) {
        cpa_wait0();
        __syncthreads();

        if (c + 1 < nchunks) {
            uint32_t nb = sb + ((c + 1) & 1) * BUFSZ;
            const char* ph = aHiBase + (c + 1) * 64;
            const char* pl = aLoBase + (c + 1) * 64;
            cpa16(nb + O_AHI + aDst,      ph,      a_bytes);
            cpa16(nb + O_AHI + aDst + 16, ph + 16, a_bytes);
            cpa16(nb + O_ALO + aDst,      pl,      a_bytes);
            cpa16(nb + O_ALO + aDst + 16, pl + 16, a_bytes);
            const char* qh = bHiBase + (c + 1) * 64;
            const char* ql = bLoBase + (c + 1) * 64;
#pragma unroll
            for (int jj = 0; jj < 4; jj++) {
                cpa16(nb + O_BHI + bDst + jj * 16, qh + jj * 16, 16);
                cpa16(nb + O_BLO + bDst + jj * 16, ql + jj * 16, 16);
            }
            cpa_commit();
        }

        const uint32_t cb = sb + (c & 1) * BUFSZ;
        const uint32_t uAhi = cb + O_AHI, uAlo = cb + O_ALO;
        const uint32_t uBhi = cb + O_BHI, uBlo = cb + O_BLO;

#pragma unroll
        for (int kt = 0; kt < 2; kt++) {
            const uint32_t aoff = (uint32_t)((kt * 32) + ((lane >> 4) * 16));
            uint32_t ah[4][4], al[4][4];
#pragma unroll
            for (int mi = 0; mi < 4; mi++) {
                uint32_t ra = (uint32_t)((mi * 16 + (lane & 15)) * ASTR) + aoff;
                ldm_x4(ah[mi], uAhi + ra);
                ldm_x4(al[mi], uAlo + ra);
            }
            uint32_t bh[8], bl[8];
#pragma unroll
            for (int bj = 0; bj < 2; bj++) {
                int nrow = wn0 + (bj * 2 + (lane >> 4)) * 8 + (lane & 7);
                uint32_t rb = (uint32_t)(nrow * ASTR) + (uint32_t)(kt * 32 + ((lane >> 3) & 1) * 16);
                ldm_x4(&bh[bj * 4], uBhi + rb);
                ldm_x4(&bl[bj * 4], uBlo + rb);
            }
#pragma unroll
            for (int mi = 0; mi < 4; mi++)
#pragma unroll
                for (int ni = 0; ni < 4; ni++) {
                    mma_bf16(acc[mi][ni], ah[mi], &bh[ni * 2]);
                    mma_bf16(acc[mi][ni], al[mi], &bh[ni * 2]);
                    mma_bf16(acc[mi][ni], ah[mi], &bl[ni * 2]);
                }
        }
    }

    // ---- epilogue: relu(acc + deg*bias) + column stats ----
    const int rsub = lane >> 2;
    const int cpair = (lane & 3) * 2;
    float cs[4][2], cq[4][2];
#pragma unroll
    for (int ni = 0; ni < 4; ni++) { cs[ni][0] = cs[ni][1] = cq[ni][0] = cq[ni][1] = 0.f; }

#pragma unroll
    for (int mi = 0; mi < 4; mi++) {
        int m0 = row0 + mi * 16 + rsub;
        int m1 = m0 + 8;
        float dg0 = (m0 < NN) ? g_deg[m0] : 0.f;
        float dg1 = (m1 < NN) ? g_deg[m1] : 0.f;
#pragma unroll
        for (int ni = 0; ni < 4; ni++) {
            int col = n0 + wn0 + ni * 8 + cpair;
            float2 bb = *(const float2*)&bias[col];
            if (m0 < NN) {
                float ox = fmaxf(acc[mi][ni][0] + dg0 * bb.x, 0.f);
                float oy = fmaxf(acc[mi][ni][1] + dg0 * bb.y, 0.f);
                float2 o = {ox, oy};
                *(float2*)&g_pre[(size_t)m0 * HID + col] = o;
                cs[ni][0] += ox; cq[ni][0] += ox * ox;
                cs[ni][1] += oy; cq[ni][1] += oy * oy;
            }
            if (m1 < NN) {
                float ox = fmaxf(acc[mi][ni][2] + dg1 * bb.x, 0.f);
                float oy = fmaxf(acc[mi][ni][3] + dg1 * bb.y, 0.f);
                float2 o = {ox, oy};
                *(float2*)&g_pre[(size_t)m1 * HID + col] = o;
                cs[ni][0] += ox; cq[ni][0] += ox * ox;
                cs[ni][1] += oy; cq[ni][1] += oy * oy;
            }
        }
    }
#pragma unroll
    for (int ni = 0; ni < 4; ni++) {
        float s0 = cs[ni][0], s1v = cs[ni][1], q0 = cq[ni][0], q1 = cq[ni][1];
#pragma unroll
        for (int off = 16; off >= 4; off >>= 1) {
            s0  += __shfl_down_sync(0xFFFFFFFF, s0, off);
            s1v += __shfl_down_sync(0xFFFFFFFF, s1v, off);
            q0  += __shfl_down_sync(0xFFFFFFFF, q0, off);
            q1  += __shfl_down_sync(0xFFFFFFFF, q1, off);
        }
        if (lane < 4) {
            int col = n0 + wn0 + ni * 8 + lane * 2;
            atomicAdd(&stats[col], s0);
            atomicAdd(&stats[col + 1], s1v);
            atomicAdd(&stats[HID + col], q0);
            atomicAdd(&stats[HID + col + 1], q1);
        }
    }
}

// ---------------- fused readout: pool(+BN) -> fc1 -> fc2 ---------------------
__global__ void __launch_bounds__(512) k_poolfc(const float* __restrict__ stats,
                                                const float* __restrict__ gamma,
                                                const float* __restrict__ beta,
                                                const float* __restrict__ neighbor,
                                                const float* __restrict__ fc1w,
                                                const float* __restrict__ fc1b,
                                                const float* __restrict__ fc2w,
                                                const float* __restrict__ fc2b,
                                                float* __restrict__ out) {
    __shared__ float zs[ZDIM];
    __shared__ float s1[MLPD];
    int b = blockIdx.x, t = threadIdx.x;
    int boff = g_boff[b], cnt = g_bcnt[b];

    if (t < HID) {
        const float inv_n = 1.0f / (float)NN;
        float s = stats[t], q = stats[HID + t];
        float mu = s * inv_n;
        float var = q * inv_n - mu * mu;
        float r = rsqrtf(var + 1e-5f);
        float sc = r * gamma[t];
        float sh = beta[t] - mu * sc;
        float accp = 0.f;
        for (int rr = 0; rr < cnt; rr++) {
            float v = g_pre[(size_t)(boff + rr) * HID + t];
            accp += fmaxf(fmaf(v, sc, sh), 0.f);
        }
        zs[t] = accp;
    } else if (t == HID) {
        zs[HID] = (float)cnt / 40.0f;
    } else if (t < HID + 1 + IN_C + 1 && t >= HID + 1) {
        int j = t - (HID + 1);
        if (j < IN_C) zs[HID + 1 + j] = neighbor[b * IN_C + j];
    }
    __syncthreads();

    float acc = fc1b[t];
    for (int k = 0; k < ZDIM; k++) acc = fmaf(zs[k], fc1w[(size_t)k * MLPD + t], acc);
    s1[t] = fmaxf(acc, 0.f);
    __syncthreads();

    if (t < 128) {
        int wrp = t >> 5, lane = t & 31;
        float a2 = 0.f;
        for (int k = lane; k < MLPD; k += 32)
            a2 = fmaf(s1[k], fc2w[(size_t)k * NCL + wrp], a2);
#pragma unroll
        for (int o = 16; o > 0; o >>= 1) a2 += __shfl_down_sync(0xFFFFFFFF, a2, o);
        if (lane == 0) out[b * NCL + wrp] = a2 + fc2b[wrp];
    }
}

// ---------------- launch -----------------------------------------------------
extern "C" void kernel_launch(void* const* d_in, const int* in_sizes, int n_in,
                              void* d_out, int out_size) {
    const float* x        = (const float*)d_in[0];
    const int*   ei       = (const int*)d_in[1];
    const float* ea       = (const float*)d_in[2];
    const int*   batch    = (const int*)d_in[3];
    const float* neighbor = (const float*)d_in[4];
    const float* W1  = (const float*)d_in[5];
    const float* b1  = (const float*)d_in[6];
    const float* g1  = (const float*)d_in[7];
    const float* be1 = (const float*)d_in[8];
    const float* W2  = (const float*)d_in[9];
    const float* b2  = (const float*)d_in[10];
    const float* g2  = (const float*)d_in[11];
    const float* be2 = (const float*)d_in[12];
    const float* W3  = (const float*)d_in[13];
    const float* b3  = (const float*)d_in[14];
    const float* g3  = (const float*)d_in[15];
    const float* be3 = (const float*)d_in[16];
    const float* fc1w = (const float*)d_in[17];
    const float* fc1b = (const float*)d_in[18];
    const float* fc2w = (const float*)d_in[19];
    const float* fc2b = (const float*)d_in[20];
    float* out = (float*)d_out;

    const int* src = ei;
    const int* dst = ei + EE;

    float* statsA; float* statsB;
    cudaGetSymbolAddress((void**)&statsA, g_statsA);
    cudaGetSymbolAddress((void**)&statsB, g_statsB);

    cudaFuncSetAttribute(k_gemm_mma, cudaFuncAttributeMaxDynamicSharedMemorySize, GEMM_SMEM);

    // setup
    k_zero<<<(NN + 255) / 256, 256>>>();
    k_hist<<<(EE + 255) / 256, 256>>>(dst, batch);
    k_scan<<<1, 1024>>>();
    k_fill<<<(EE + 255) / 256, 256>>>(src, dst);
    k_wprep_all<<<dim3((KMAX * HID + 255) / 256, 3), 256>>>(W1, W2, W3);

    dim3 ggrid((NN + BM - 1) / BM, HID / BN);
    int K1 = 2 * IN_C + ECH;   // 320
    int K23 = 2 * HID + ECH;   // 576

    // layer 1 (features + edge_attr fused)
    k_agg1<<<NN / 4, 128>>>(x, statsA, ea);
    k_gemm_mma<<<ggrid, 128, GEMM_SMEM>>>(b1, K1, 0, statsA);

    // layer 2
    k_agg_bn<<<NN / 2, 128>>>(g1, be1, statsA, statsB);
    k_gemm_mma<<<ggrid, 128, GEMM_SMEM>>>(b2, K23, 1, statsB);

    // layer 3
    k_agg_bn<<<NN / 2, 128>>>(g2, be2, statsB, statsA);
    k_gemm_mma<<<ggrid, 128, GEMM_SMEM>>>(b3, K23, 2, statsA);

    // readout
    k_poolfc<<<BB, 512>>>(statsA, g3, be3, neighbor, fc1w, fc1b, fc2w, fc2b, out);
}